// round 15
// baseline (speedup 1.0000x reference)
#include <cuda_runtime.h>
#include <cuda_bf16.h>
#include <cstddef>

#define ROWS   128
#define T      30
#define OUT_T  26
#define NPAIRS 8256
#define NTHREADS 768
#define NWARPS   24
#define UNITS    320        // 10 tiles * 32 i-iterations

#define XS_STRIDE 36        // 144 B rows: 16B-aligned for float4 broadcast loads
#define STG_STRIDE 33       // k-major staging stride (odd -> conflict-free)
#define STG_WORDS (OUT_T * STG_STRIDE)   // 858

__device__ __forceinline__ int pair_offset(int i) {
    return i * ROWS - (i * (i - 1)) / 2;
}

__device__ __forceinline__ int div26(int w) {   // exact floor(w/26) for 0<=w<832
    return (w * 10083) >> 18;
}

__global__ __launch_bounds__(NTHREADS, 1)
void ts_cov_kernel(const float* __restrict__ in, float* __restrict__ out) {
    const int batch = blockIdx.x;

    __shared__ float xs[ROWS * XS_STRIDE];          // 18432 B
    __shared__ float stage[NWARPS * STG_WORDS];     // 82368 B (doubles as raw staging)

    // ---- Stage raw input (coalesced) ----
    const float* gin = in + (size_t)batch * (ROWS * T);
    for (int idx = threadIdx.x; idx < ROWS * T; idx += NTHREADS)
        stage[idx] = gin[idx];
    __syncthreads();

    // ---- Per-row normalization (population std) ----
    if (threadIdx.x < ROWS) {
        const int r = threadIdx.x;
        float s = 0.f;
#pragma unroll
        for (int t = 0; t < T; t++) s += stage[r * T + t];
        const float mean = s * (1.0f / T);
        float v = 0.f;
#pragma unroll
        for (int t = 0; t < T; t++) {
            float c = stage[r * T + t] - mean;
            v += c * c;
        }
        const float inv = rsqrtf(v * (1.0f / T));
#pragma unroll
        for (int t = 0; t < T; t++)
            xs[r * XS_STRIDE + t] = (stage[r * T + t] - mean) * inv;
    }
    __syncthreads();   // xs ready; stage[] reused as per-warp staging

    const int wid  = threadIdx.x >> 5;
    const int lane = threadIdx.x & 31;
    float* sw = stage + wid * STG_WORDS;
    float* gout = out + (size_t)batch * ((size_t)NPAIRS * OUT_T);

    // Proportional contiguous unit ranges: 13 or 14 units per warp.
    const int uA = (wid * UNITS) / NWARPS;
    const int uB = ((wid + 1) * UNITS) / NWARPS;

    for (int tile = (uA >> 5); tile <= ((uB - 1) >> 5); ++tile) {
        // tile -> (jb, is), triangular enumeration with is <= jb
        const int jb = (tile >= 6) ? 3 : (tile >= 3) ? 2 : (tile >= 1) ? 1 : 0;
        const int is = tile - (jb * (jb + 1)) / 2;
        const int j0 = jb * 32;

        // b row (j0+lane) register-resident for this tile (float4 loads)
        float b[T];
        {
            const float4* bp = (const float4*)(xs + (j0 + lane) * XS_STRIDE);
#pragma unroll
            for (int m = 0; m < 7; m++) {
                float4 v4 = bp[m];
                b[m * 4 + 0] = v4.x; b[m * 4 + 1] = v4.y;
                b[m * 4 + 2] = v4.z; b[m * 4 + 3] = v4.w;
            }
            float2 v2 = *(const float2*)(xs + (j0 + lane) * XS_STRIDE + 28);
            b[28] = v2.x; b[29] = v2.y;
        }

        const int loU = max(uA, tile * 32);
        const int hiU = min(uB, tile * 32 + 32);

        for (int u = loU; u < hiU; ++u) {
            const int i = is * 32 + (u - tile * 32);
            const float4* ap = (const float4*)(xs + i * XS_STRIDE);

            // Ring-buffer sliding window (low register footprint):
            // ring[t%5] = p[t] = a[t]*b[t]; step k replaces slot (k+4)%5.
            float ring[5];
            float4 a4 = ap[0];                       // t = 0..3
            ring[0] = a4.x * b[0];
            ring[1] = a4.y * b[1];
            ring[2] = a4.z * b[2];
            ring[3] = a4.w * b[3];
            a4 = ap[1];                              // t = 4..7
            ring[4] = a4.x * b[4];

            float s = ring[0] + ring[1] + ring[2] + ring[3] + ring[4];
            sw[lane] = s * 0.2f;                     // res[0]
            {
                float pn;
                pn = a4.y * b[5]; s += pn - ring[0]; ring[0] = pn;   // k=1
                sw[1 * STG_STRIDE + lane] = s * 0.2f;
                pn = a4.z * b[6]; s += pn - ring[1]; ring[1] = pn;   // k=2
                sw[2 * STG_STRIDE + lane] = s * 0.2f;
                pn = a4.w * b[7]; s += pn - ring[2]; ring[2] = pn;   // k=3
                sw[3 * STG_STRIDE + lane] = s * 0.2f;
            }
#pragma unroll
            for (int c = 2; c < 8; c++) {            // k = 4..25
                a4 = ap[c];                          // t = 4c..4c+3
                const int k0 = 4 * c - 4;
                float pn;
                pn = a4.x * b[4 * c + 0]; s += pn - ring[(k0 + 4) % 5]; ring[(k0 + 4) % 5] = pn;
                sw[(k0 + 0) * STG_STRIDE + lane] = s * 0.2f;
                pn = a4.y * b[4 * c + 1]; s += pn - ring[(k0 + 5) % 5]; ring[(k0 + 5) % 5] = pn;
                sw[(k0 + 1) * STG_STRIDE + lane] = s * 0.2f;
                if (c < 7) {
                    pn = a4.z * b[4 * c + 2]; s += pn - ring[(k0 + 6) % 5]; ring[(k0 + 6) % 5] = pn;
                    sw[(k0 + 2) * STG_STRIDE + lane] = s * 0.2f;
                    pn = a4.w * b[4 * c + 3]; s += pn - ring[(k0 + 7) % 5]; ring[(k0 + 7) % 5] = pn;
                    sw[(k0 + 3) * STG_STRIDE + lane] = s * 0.2f;
                }
            }
            __syncwarp();

            // Coalesced copy-out
            const int lo = (i > j0) ? (i - j0) : 0;
            const size_t p_start = (size_t)pair_offset(i) + (size_t)(j0 + lo - i);
            float* basep = gout + p_start * OUT_T;

            if (lo == 0) {
                // full tile: 832 floats = 416 float2, 13 warp batches.
                // w even -> k = w-26q even <= 24, so (k,k+1) share pair q.
#pragma unroll
                for (int m = 0; m < 13; m++) {
                    const int w = 2 * (m * 32 + lane);
                    const int q = div26(w);
                    const int k = w - q * OUT_T;
                    float2 v = make_float2(sw[k * STG_STRIDE + q],
                                           sw[(k + 1) * STG_STRIDE + q]);
                    *(float2*)(basep + w) = v;
                }
            } else {
                const int total = (32 - lo) * OUT_T;
#pragma unroll
                for (int m = 0; m < OUT_T; m++) {
                    const int w = m * 32 + lane;
                    if (w < total) {
                        const int q = div26(w);
                        const int k = w - q * OUT_T;
                        basep[w] = sw[k * STG_STRIDE + lo + q];
                    }
                }
            }
            __syncwarp();   // protect sw before next iteration's STS
        }
    }
}

extern "C" void kernel_launch(void* const* d_in, const int* in_sizes, int n_in,
                              void* d_out, int out_size) {
    const float* in = (const float*)d_in[0];
    float* out = (float*)d_out;
    const int B = in_sizes[0] / (ROWS * T);
    ts_cov_kernel<<<B, NTHREADS>>>(in, out);
}

// round 16
// speedup vs baseline: 1.0346x; 1.0346x over previous
#include <cuda_runtime.h>
#include <cuda_bf16.h>
#include <cstddef>

#define ROWS   128
#define T      30
#define OUT_T  26
#define NPAIRS 8256
#define NTHREADS 640
#define NWARPS   20
#define UNITS    320        // 10 tiles * 32 i-iterations
#define UPW      (UNITS / NWARPS)   // 16 units per warp

#define XS_STRIDE 36        // 144 B rows: 16B-aligned for float4 broadcast loads
#define STG_STRIDE 33       // k-major staging stride (odd -> conflict-free)
#define STG_WORDS (OUT_T * STG_STRIDE)   // 858

__device__ __forceinline__ int pair_offset(int i) {
    return i * ROWS - (i * (i - 1)) / 2;
}

__device__ __forceinline__ int div26(int w) {   // exact floor(w/26) for 0<=w<832
    return (w * 10083) >> 18;
}

__global__ __launch_bounds__(NTHREADS, 1)
void ts_cov_kernel(const float* __restrict__ in, float* __restrict__ out) {
    const int batch = blockIdx.x;

    __shared__ float xs[ROWS * XS_STRIDE];          // 18432 B
    __shared__ float stage[NWARPS * STG_WORDS];     // 68640 B (doubles as raw staging)

    // ---- Stage raw input (coalesced) ----
    const float* gin = in + (size_t)batch * (ROWS * T);
    for (int idx = threadIdx.x; idx < ROWS * T; idx += NTHREADS)
        stage[idx] = gin[idx];
    __syncthreads();

    // ---- Per-row normalization (population std) ----
    if (threadIdx.x < ROWS) {
        const int r = threadIdx.x;
        float s = 0.f;
#pragma unroll
        for (int t = 0; t < T; t++) s += stage[r * T + t];
        const float mean = s * (1.0f / T);
        float v = 0.f;
#pragma unroll
        for (int t = 0; t < T; t++) {
            float c = stage[r * T + t] - mean;
            v += c * c;
        }
        const float inv = rsqrtf(v * (1.0f / T));
#pragma unroll
        for (int t = 0; t < T; t++)
            xs[r * XS_STRIDE + t] = (stage[r * T + t] - mean) * inv;
    }
    __syncthreads();   // xs ready; stage[] reused as per-warp staging

    const int wid  = threadIdx.x >> 5;
    const int lane = threadIdx.x & 31;
    float* sw = stage + wid * STG_WORDS;
    float* gout = out + (size_t)batch * ((size_t)NPAIRS * OUT_T);

    const int uA = wid * UPW;
    const int uB = uA + UPW;

    for (int tile = (uA >> 5); tile <= ((uB - 1) >> 5); ++tile) {
        // tile -> (jb, is), triangular enumeration with is <= jb
        const int jb = (tile >= 6) ? 3 : (tile >= 3) ? 2 : (tile >= 1) ? 1 : 0;
        const int is = tile - (jb * (jb + 1)) / 2;
        const int j0 = jb * 32;

        // b row (j0+lane) register-resident for this tile (float4 loads)
        float b[T];
        {
            const float4* bp = (const float4*)(xs + (j0 + lane) * XS_STRIDE);
#pragma unroll
            for (int m = 0; m < 7; m++) {
                float4 v4 = bp[m];
                b[m * 4 + 0] = v4.x; b[m * 4 + 1] = v4.y;
                b[m * 4 + 2] = v4.z; b[m * 4 + 3] = v4.w;
            }
            float2 v2 = *(const float2*)(xs + (j0 + lane) * XS_STRIDE + 28);
            b[28] = v2.x; b[29] = v2.y;
        }

        const int loU = max(uA, tile * 32);
        const int hiU = min(uB, tile * 32 + 32);

        for (int u = loU; u < hiU; ++u) {
            const int i = is * 32 + (u - tile * 32);
            const float4* ap = (const float4*)(xs + i * XS_STRIDE);

            // Two independent sliding-window chains (k=0..12 and k=13..25),
            // each a 5-slot ring recurrence. Halves the serial FADD chain.
            float4 c0 = ap[0], c1 = ap[1], c2 = ap[2], c3 = ap[3], c4 = ap[4];

            // ---- chain A: seed window k=0 (t=0..4) ----
            float rA0 = c0.x * b[0], rA1 = c0.y * b[1], rA2 = c0.z * b[2];
            float rA3 = c0.w * b[3], rA4 = c1.x * b[4];
            float sA = rA0 + rA1 + rA2 + rA3 + rA4;
            sw[lane] = sA * 0.2f;                      // res[0]

            // ---- chain B: seed window k=13 (t=13..17); ring[t%5] ----
            float rB3 = c3.y * b[13], rB4 = c3.z * b[14], rB0 = c3.w * b[15];
            float rB1 = c4.x * b[16], rB2 = c4.y * b[17];
            float sB = rB3 + rB4 + rB0 + rB1 + rB2;
            sw[13 * STG_STRIDE + lane] = sB * 0.2f;    // res[13]

            float4 c5 = ap[5], c6 = ap[6], c7 = ap[7];
            float pn;
            // chain A k=1..12 (t_new = 5..16); exiting slot = (k+4)%5
            pn = c1.y * b[5];  sA += pn - rA0; rA0 = pn; sw[ 1 * STG_STRIDE + lane] = sA * 0.2f;
            pn = c4.z * b[18]; sB += pn - rB3; rB3 = pn; sw[14 * STG_STRIDE + lane] = sB * 0.2f;
            pn = c1.z * b[6];  sA += pn - rA1; rA1 = pn; sw[ 2 * STG_STRIDE + lane] = sA * 0.2f;
            pn = c4.w * b[19]; sB += pn - rB4; rB4 = pn; sw[15 * STG_STRIDE + lane] = sB * 0.2f;
            pn = c1.w * b[7];  sA += pn - rA2; rA2 = pn; sw[ 3 * STG_STRIDE + lane] = sA * 0.2f;
            pn = c5.x * b[20]; sB += pn - rB0; rB0 = pn; sw[16 * STG_STRIDE + lane] = sB * 0.2f;
            pn = c2.x * b[8];  sA += pn - rA3; rA3 = pn; sw[ 4 * STG_STRIDE + lane] = sA * 0.2f;
            pn = c5.y * b[21]; sB += pn - rB1; rB1 = pn; sw[17 * STG_STRIDE + lane] = sB * 0.2f;
            pn = c2.y * b[9];  sA += pn - rA4; rA4 = pn; sw[ 5 * STG_STRIDE + lane] = sA * 0.2f;
            pn = c5.z * b[22]; sB += pn - rB2; rB2 = pn; sw[18 * STG_STRIDE + lane] = sB * 0.2f;
            pn = c2.z * b[10]; sA += pn - rA0; rA0 = pn; sw[ 6 * STG_STRIDE + lane] = sA * 0.2f;
            pn = c5.w * b[23]; sB += pn - rB3; rB3 = pn; sw[19 * STG_STRIDE + lane] = sB * 0.2f;
            pn = c2.w * b[11]; sA += pn - rA1; rA1 = pn; sw[ 7 * STG_STRIDE + lane] = sA * 0.2f;
            pn = c6.x * b[24]; sB += pn - rB4; rB4 = pn; sw[20 * STG_STRIDE + lane] = sB * 0.2f;
            pn = c3.x * b[12]; sA += pn - rA2; rA2 = pn; sw[ 8 * STG_STRIDE + lane] = sA * 0.2f;
            pn = c6.y * b[25]; sB += pn - rB0; rB0 = pn; sw[21 * STG_STRIDE + lane] = sB * 0.2f;
            pn = c3.y * b[13]; sA += pn - rA3; rA3 = pn; sw[ 9 * STG_STRIDE + lane] = sA * 0.2f;
            pn = c6.z * b[26]; sB += pn - rB1; rB1 = pn; sw[22 * STG_STRIDE + lane] = sB * 0.2f;
            pn = c3.z * b[14]; sA += pn - rA4; rA4 = pn; sw[10 * STG_STRIDE + lane] = sA * 0.2f;
            pn = c6.w * b[27]; sB += pn - rB2; rB2 = pn; sw[23 * STG_STRIDE + lane] = sB * 0.2f;
            pn = c3.w * b[15]; sA += pn - rA0; rA0 = pn; sw[11 * STG_STRIDE + lane] = sA * 0.2f;
            pn = c7.x * b[28]; sB += pn - rB3; rB3 = pn; sw[24 * STG_STRIDE + lane] = sB * 0.2f;
            pn = c4.x * b[16]; sA += pn - rA1; rA1 = pn; sw[12 * STG_STRIDE + lane] = sA * 0.2f;
            pn = c7.y * b[29]; sB += pn - rB4; rB4 = pn; sw[25 * STG_STRIDE + lane] = sB * 0.2f;

            __syncwarp();

            // Coalesced copy-out (exact R14 pattern)
            const int lo = (i > j0) ? (i - j0) : 0;
            const size_t p_start = (size_t)pair_offset(i) + (size_t)(j0 + lo - i);
            float* basep = gout + p_start * OUT_T;

            if (lo == 0) {
                // full tile: 832 floats = 416 float2, 13 warp batches.
#pragma unroll
                for (int m = 0; m < 13; m++) {
                    const int w = 2 * (m * 32 + lane);
                    const int q = div26(w);
                    const int k = w - q * OUT_T;
                    float2 v = make_float2(sw[k * STG_STRIDE + q],
                                           sw[(k + 1) * STG_STRIDE + q]);
                    *(float2*)(basep + w) = v;
                }
            } else {
                const int total = (32 - lo) * OUT_T;
#pragma unroll
                for (int m = 0; m < OUT_T; m++) {
                    const int w = m * 32 + lane;
                    if (w < total) {
                        const int q = div26(w);
                        const int k = w - q * OUT_T;
                        basep[w] = sw[k * STG_STRIDE + lo + q];
                    }
                }
            }
            __syncwarp();   // protect sw before next iteration's STS
        }
    }
}

extern "C" void kernel_launch(void* const* d_in, const int* in_sizes, int n_in,
                              void* d_out, int out_size) {
    const float* in = (const float*)d_in[0];
    float* out = (float*)d_out;
    const int B = in_sizes[0] / (ROWS * T);
    ts_cov_kernel<<<B, NTHREADS>>>(in, out);
}